// round 8
// baseline (speedup 1.0000x reference)
#include <cuda_runtime.h>
#include <cuda_bf16.h>

#define N_NEURONS   100000
#define INPUT_SIZE  1024
#define OUTPUT_SIZE 256
#define E_EDGES     10000000
#define STEPS       3

#define CLUSTER_SZ  4
#define VCHUNK      25000              // floats of v per CTA (100 KB)
#define VSMEM_BYTES (VCHUNK * 4)

// Persistent state in __device__ globals (no allocation allowed).
__device__ float g_v[N_NEURONS];    // current neuron values
__device__ float g_acc[N_NEURONS];  // accumulator, pre-seeded with biases

// ---------------------------------------------------------------------------
// Init: acc = [0..., biases].  (g_v is written by post before it is read.)
// ---------------------------------------------------------------------------
__global__ void init_kernel(const float* __restrict__ bias) {
    int i = blockIdx.x * blockDim.x + threadIdx.x;
    if (i < N_NEURONS) {
        g_acc[i] = (i < INPUT_SIZE) ? 0.0f : bias[i - INPUT_SIZE];
    }
}

// ---------------------------------------------------------------------------
// Step-1 edge pass: v is zero except v[0:1024] = x, so only ~1% of edges are
// live. Stream src only; touch w/dst/acc only for live edges.
// ---------------------------------------------------------------------------
__global__ void __launch_bounds__(256)
edge_step1_kernel(const float* __restrict__ x,
                  const float* __restrict__ w,
                  const int*   __restrict__ src,
                  const int*   __restrict__ dst) {
    const int nvec = E_EDGES / 4;
    int i = blockIdx.x * blockDim.x + threadIdx.x;
    if (i >= nvec) return;

    int4 s = __ldg(&((const int4*)src)[i]);
    int  e = i * 4;

    if (s.x < INPUT_SIZE) {
        float m = __ldg(&x[s.x]) * __ldg(&w[e + 0]);
        atomicAdd(&g_acc[__ldg(&dst[e + 0])], m);
    }
    if (s.y < INPUT_SIZE) {
        float m = __ldg(&x[s.y]) * __ldg(&w[e + 1]);
        atomicAdd(&g_acc[__ldg(&dst[e + 1])], m);
    }
    if (s.z < INPUT_SIZE) {
        float m = __ldg(&x[s.z]) * __ldg(&w[e + 2]);
        atomicAdd(&g_acc[__ldg(&dst[e + 2])], m);
    }
    if (s.w < INPUT_SIZE) {
        float m = __ldg(&x[s.w]) * __ldg(&w[e + 3]);
        atomicAdd(&g_acc[__ldg(&dst[e + 3])], m);
    }
}

// ---------------------------------------------------------------------------
// Cluster gather: v distributed across 4 cluster CTAs (25K floats each).
// mapa + ld.shared::cluster resolves any neuron index in one DSMEM access.
// ---------------------------------------------------------------------------
__device__ __forceinline__ float cluster_gather(unsigned sbase, int s) {
    unsigned us    = (unsigned)s;
    unsigned owner = us / (unsigned)VCHUNK;                    // 0..3
    unsigned laddr = sbase + (us - owner * (unsigned)VCHUNK) * 4u;
    unsigned raddr;
    float    v;
    asm("mapa.shared::cluster.u32 %0, %1, %2;"
        : "=r"(raddr) : "r"(laddr), "r"(owner));
    asm volatile("ld.shared::cluster.f32 %0, [%1];"
        : "=f"(v) : "r"(raddr));
    return v;
}

// ---------------------------------------------------------------------------
// Steps 2-3 edge pass: single sweep over all edges. Each cluster CTA holds a
// quarter of v in smem; gathers served by DSMEM; scatter via RED to g_acc.
// 100KB smem/CTA -> 2 CTAs/SM -> 2048 threads/SM (regs capped at 32).
// ---------------------------------------------------------------------------
__global__ void __launch_bounds__(1024, 2)
edge_cluster_kernel(const float* __restrict__ w,
                    const int*   __restrict__ src,
                    const int*   __restrict__ dst) {
    extern __shared__ float sv[];

    unsigned rank;
    asm("mov.u32 %0, %%cluster_ctarank;" : "=r"(rank));
    unsigned sbase;
    {
        unsigned long long t;
        asm("cvta.to.shared.u64 %0, %1;" : "=l"(t) : "l"(sv));
        sbase = (unsigned)t;
    }

    // Fill this CTA's quarter of v (float4 coalesced; offsets 16B-aligned).
    {
        const float4* vsrc = (const float4*)(g_v + rank * VCHUNK);
        float4*       vdst = (float4*)sv;
        for (int j = threadIdx.x; j < VCHUNK / 4; j += blockDim.x)
            vdst[j] = vsrc[j];
    }
    asm volatile("barrier.cluster.arrive.aligned;" ::: "memory");
    asm volatile("barrier.cluster.wait.aligned;" ::: "memory");

    const int4*   src4 = (const int4*)src;
    const int4*   dst4 = (const int4*)dst;
    const float4* w4   = (const float4*)w;
    const int nvec   = E_EDGES / 4;
    const int stride = gridDim.x * blockDim.x;

    for (int i = blockIdx.x * blockDim.x + threadIdx.x; i < nvec; i += stride) {
        int4   s  = __ldg(&src4[i]);
        int4   d  = __ldg(&dst4[i]);
        float4 ww = __ldg(&w4[i]);

        float v0 = cluster_gather(sbase, s.x);
        float v1 = cluster_gather(sbase, s.y);
        float v2 = cluster_gather(sbase, s.z);
        float v3 = cluster_gather(sbase, s.w);

        atomicAdd(&g_acc[d.x], v0 * ww.x);
        atomicAdd(&g_acc[d.y], v1 * ww.y);
        atomicAdd(&g_acc[d.z], v2 * ww.z);
        atomicAdd(&g_acc[d.w], v3 * ww.w);
    }

    // No CTA may exit while peers can still read its smem.
    asm volatile("barrier.cluster.arrive.aligned;" ::: "memory");
    asm volatile("barrier.cluster.wait.aligned;" ::: "memory");
}

// ---------------------------------------------------------------------------
// Post pass: v = tanh(acc) (except outputs), re-seed acc with biases,
// optionally emit the output slice.
// ---------------------------------------------------------------------------
__global__ void post_kernel(const float* __restrict__ bias,
                            float* __restrict__ out,
                            int write_out) {
    int i = blockIdx.x * blockDim.x + threadIdx.x;
    if (i < N_NEURONS) {
        float a = g_acc[i];
        float v = (i < N_NEURONS - OUTPUT_SIZE) ? tanhf(a) : a;
        g_v[i]   = v;
        g_acc[i] = (i < INPUT_SIZE) ? 0.0f : bias[i - INPUT_SIZE];
        if (write_out && i >= N_NEURONS - OUTPUT_SIZE) {
            out[i - (N_NEURONS - OUTPUT_SIZE)] = v;
        }
    }
}

// ---------------------------------------------------------------------------
// Launcher — graph-capturable: kernel launches only.
// Input order: x, synapse_weights, neuron_biases, synapse_src, synapse_dst
// ---------------------------------------------------------------------------
extern "C" void kernel_launch(void* const* d_in, const int* in_sizes, int n_in,
                              void* d_out, int out_size) {
    const float* x    = (const float*)d_in[0];
    const float* w    = (const float*)d_in[1];
    const float* bias = (const float*)d_in[2];
    const int*   src  = (const int*)d_in[3];
    const int*   dst  = (const int*)d_in[4];
    float* out = (float*)d_out;

    cudaFuncSetAttribute(edge_cluster_kernel,
                         cudaFuncAttributeMaxDynamicSharedMemorySize,
                         VSMEM_BYTES);

    const int tpbN  = 256;
    const int gridN = (N_NEURONS + tpbN - 1) / tpbN;

    const int nvec  = E_EDGES / 4;
    const int tpbE  = 256;
    const int gridE = (nvec + tpbE - 1) / tpbE;

    init_kernel<<<gridN, tpbN>>>(bias);

    // Step 1: input-sparse edge pass
    edge_step1_kernel<<<gridE, tpbE>>>(x, w, src, dst);
    post_kernel<<<gridN, tpbN>>>(bias, out, 0);

    // Steps 2..3: clustered single-pass edge sweep
    cudaLaunchConfig_t cfg = {};
    cfg.gridDim          = dim3(296, 1, 1);    // 2 CTAs/SM over 148 SMs
    cfg.blockDim         = dim3(1024, 1, 1);
    cfg.dynamicSmemBytes = VSMEM_BYTES;
    cudaLaunchAttribute attrs[1];
    attrs[0].id = cudaLaunchAttributeClusterDimension;
    attrs[0].val.clusterDim = {CLUSTER_SZ, 1, 1};
    cfg.attrs    = attrs;
    cfg.numAttrs = 1;

    for (int step = 1; step < STEPS; ++step) {
        cudaLaunchKernelEx(&cfg, edge_cluster_kernel, w, src, dst);
        post_kernel<<<gridN, tpbN>>>(bias, out, step == STEPS - 1 ? 1 : 0);
    }
}

// round 9
// speedup vs baseline: 2.0129x; 2.0129x over previous
#include <cuda_runtime.h>
#include <cuda_bf16.h>

#define N_NEURONS   100000
#define INPUT_SIZE  1024
#define OUTPUT_SIZE 256
#define E_EDGES     10000000
#define STEPS       3

#define CHUNK       50000            // floats of v per smem chunk (200 KB)
#define NCHUNKS     2
#define SMEM_BYTES  (CHUNK * 4)

// Persistent state in __device__ globals (no allocation allowed).
__device__ float g_v[N_NEURONS];    // current neuron values
__device__ float g_acc[N_NEURONS];  // accumulator, pre-seeded with biases

// ---------------------------------------------------------------------------
// Init: acc = [0..., biases].  (g_v is written by post before it is read.)
// ---------------------------------------------------------------------------
__global__ void init_kernel(const float* __restrict__ bias) {
    int i = blockIdx.x * blockDim.x + threadIdx.x;
    if (i < N_NEURONS) {
        g_acc[i] = (i < INPUT_SIZE) ? 0.0f : bias[i - INPUT_SIZE];
    }
}

// ---------------------------------------------------------------------------
// Step-1 edge pass: v is zero except v[0:1024] = x, so only ~1% of edges are
// live. Stream src only; touch w/dst/acc only for live edges.
// ---------------------------------------------------------------------------
__global__ void __launch_bounds__(256)
edge_step1_kernel(const float* __restrict__ x,
                  const float* __restrict__ w,
                  const int*   __restrict__ src,
                  const int*   __restrict__ dst) {
    const int nvec = E_EDGES / 4;
    int i = blockIdx.x * blockDim.x + threadIdx.x;
    if (i >= nvec) return;

    int4 s = __ldg(&((const int4*)src)[i]);
    int  e = i * 4;

    if (s.x < INPUT_SIZE) {
        float m = __ldg(&x[s.x]) * __ldg(&w[e + 0]);
        atomicAdd(&g_acc[__ldg(&dst[e + 0])], m);
    }
    if (s.y < INPUT_SIZE) {
        float m = __ldg(&x[s.y]) * __ldg(&w[e + 1]);
        atomicAdd(&g_acc[__ldg(&dst[e + 1])], m);
    }
    if (s.z < INPUT_SIZE) {
        float m = __ldg(&x[s.z]) * __ldg(&w[e + 2]);
        atomicAdd(&g_acc[__ldg(&dst[e + 2])], m);
    }
    if (s.w < INPUT_SIZE) {
        float m = __ldg(&x[s.w]) * __ldg(&w[e + 3]);
        atomicAdd(&g_acc[__ldg(&dst[e + 3])], m);
    }
}

// ---------------------------------------------------------------------------
// Steps 2-3 edge pass: v served from smem in NCHUNKS passes, 8 edges per
// thread-iteration, software-pipelined stream loads (prefetch next group
// before processing current) to hide DRAM latency at occ=50%.
// ---------------------------------------------------------------------------
struct EdgeGroup8 {
    int4   s0, s1;
    int4   d0, d1;
    float4 w0, w1;
};

__device__ __forceinline__ void load_group8(const int4* __restrict__ src4,
                                            const int4* __restrict__ dst4,
                                            const float4* __restrict__ w4,
                                            int j, EdgeGroup8& g) {
    g.s0 = __ldg(&src4[2 * j]);
    g.s1 = __ldg(&src4[2 * j + 1]);
    g.d0 = __ldg(&dst4[2 * j]);
    g.d1 = __ldg(&dst4[2 * j + 1]);
    g.w0 = __ldg(&w4[2 * j]);
    g.w1 = __ldg(&w4[2 * j + 1]);
}

__device__ __forceinline__ void proc_edge(const float* __restrict__ sv,
                                          int base, int s, int d, float ww) {
    unsigned r = (unsigned)(s - base);
    if (r < CHUNK) atomicAdd(&g_acc[d], sv[r] * ww);
}

__device__ __forceinline__ void proc_group8(const float* __restrict__ sv,
                                            int base, const EdgeGroup8& g) {
    proc_edge(sv, base, g.s0.x, g.d0.x, g.w0.x);
    proc_edge(sv, base, g.s0.y, g.d0.y, g.w0.y);
    proc_edge(sv, base, g.s0.z, g.d0.z, g.w0.z);
    proc_edge(sv, base, g.s0.w, g.d0.w, g.w0.w);
    proc_edge(sv, base, g.s1.x, g.d1.x, g.w1.x);
    proc_edge(sv, base, g.s1.y, g.d1.y, g.w1.y);
    proc_edge(sv, base, g.s1.z, g.d1.z, g.w1.z);
    proc_edge(sv, base, g.s1.w, g.d1.w, g.w1.w);
}

__global__ void __launch_bounds__(1024, 1)
edge_smem_kernel(const float* __restrict__ w,
                 const int*   __restrict__ src,
                 const int*   __restrict__ dst) {
    extern __shared__ float sv[];   // CHUNK floats

    const int4*   src4 = (const int4*)src;
    const int4*   dst4 = (const int4*)dst;
    const float4* w4   = (const float4*)w;
    const int nvec8  = E_EDGES / 8;
    const int stride = gridDim.x * blockDim.x;
    const int tid0   = blockIdx.x * blockDim.x + threadIdx.x;

    for (int c = 0; c < NCHUNKS; ++c) {
        const int base = c * CHUNK;

        // Load this v-chunk into smem (float4 coalesced).
        {
            const float4* vsrc = (const float4*)(g_v + base);
            float4*       vdst = (float4*)sv;
            for (int j = threadIdx.x; j < CHUNK / 4; j += blockDim.x)
                vdst[j] = vsrc[j];
        }
        __syncthreads();

        int j = tid0;
        if (j < nvec8) {
            EdgeGroup8 cur;
            load_group8(src4, dst4, w4, j, cur);
            for (;;) {
                int  jn   = j + stride;
                bool more = jn < nvec8;
                EdgeGroup8 nxt;
                if (more) load_group8(src4, dst4, w4, jn, nxt);  // prefetch
                proc_group8(sv, base, cur);                      // overlap
                if (!more) break;
                cur = nxt;
                j   = jn;
            }
        }
        __syncthreads();
    }
}

// ---------------------------------------------------------------------------
// Post pass: v = tanh(acc) (except outputs), re-seed acc with biases,
// optionally emit the output slice.
// ---------------------------------------------------------------------------
__global__ void post_kernel(const float* __restrict__ bias,
                            float* __restrict__ out,
                            int write_out) {
    int i = blockIdx.x * blockDim.x + threadIdx.x;
    if (i < N_NEURONS) {
        float a = g_acc[i];
        float v = (i < N_NEURONS - OUTPUT_SIZE) ? tanhf(a) : a;
        g_v[i]   = v;
        g_acc[i] = (i < INPUT_SIZE) ? 0.0f : bias[i - INPUT_SIZE];
        if (write_out && i >= N_NEURONS - OUTPUT_SIZE) {
            out[i - (N_NEURONS - OUTPUT_SIZE)] = v;
        }
    }
}

// ---------------------------------------------------------------------------
// Launcher — graph-capturable: kernel launches only.
// Input order: x, synapse_weights, neuron_biases, synapse_src, synapse_dst
// ---------------------------------------------------------------------------
extern "C" void kernel_launch(void* const* d_in, const int* in_sizes, int n_in,
                              void* d_out, int out_size) {
    const float* x    = (const float*)d_in[0];
    const float* w    = (const float*)d_in[1];
    const float* bias = (const float*)d_in[2];
    const int*   src  = (const int*)d_in[3];
    const int*   dst  = (const int*)d_in[4];
    float* out = (float*)d_out;

    cudaFuncSetAttribute(edge_smem_kernel,
                         cudaFuncAttributeMaxDynamicSharedMemorySize,
                         SMEM_BYTES);

    const int tpbN  = 256;
    const int gridN = (N_NEURONS + tpbN - 1) / tpbN;

    const int nvec  = E_EDGES / 4;
    const int tpbE  = 256;
    const int gridE = (nvec + tpbE - 1) / tpbE;

    init_kernel<<<gridN, tpbN>>>(bias);

    // Step 1: input-sparse edge pass
    edge_step1_kernel<<<gridE, tpbE>>>(x, w, src, dst);
    post_kernel<<<gridN, tpbN>>>(bias, out, 0);

    // Steps 2..3: dense edge pass with smem-resident v + pipelined stream
    for (int step = 1; step < STEPS; ++step) {
        edge_smem_kernel<<<148, 1024, SMEM_BYTES>>>(w, src, dst);
        post_kernel<<<gridN, tpbN>>>(bias, out, step == STEPS - 1 ? 1 : 0);
    }
}

// round 10
// speedup vs baseline: 2.3898x; 1.1872x over previous
#include <cuda_runtime.h>
#include <cuda_fp16.h>
#include <cuda_bf16.h>

#define N_NEURONS   100000
#define INPUT_SIZE  1024
#define OUTPUT_SIZE 256
#define E_EDGES     10000000
#define STEPS       3

#define VSMEM_BYTES (N_NEURONS * 2)   // 200,000 B: ALL of v as fp16 in smem

// Persistent state in __device__ globals (no allocation allowed).
__device__ float  g_v[N_NEURONS];     // current neuron values (fp32, exact)
__device__ __half g_vh[N_NEURONS];    // fp16 mirror for the smem gather path
__device__ float  g_acc[N_NEURONS];   // accumulator, pre-seeded with biases

// ---------------------------------------------------------------------------
// Init: acc = [0..., biases].  (g_v / g_vh are written by post before read.)
// ---------------------------------------------------------------------------
__global__ void init_kernel(const float* __restrict__ bias) {
    int i = blockIdx.x * blockDim.x + threadIdx.x;
    if (i < N_NEURONS) {
        g_acc[i] = (i < INPUT_SIZE) ? 0.0f : bias[i - INPUT_SIZE];
    }
}

// ---------------------------------------------------------------------------
// Step-1 edge pass: v is zero except v[0:1024] = x, so only ~1% of edges are
// live. Stream src only; touch w/dst/acc only for live edges. Full fp32.
// ---------------------------------------------------------------------------
__global__ void __launch_bounds__(256)
edge_step1_kernel(const float* __restrict__ x,
                  const float* __restrict__ w,
                  const int*   __restrict__ src,
                  const int*   __restrict__ dst) {
    const int nvec = E_EDGES / 4;
    int i = blockIdx.x * blockDim.x + threadIdx.x;
    if (i >= nvec) return;

    int4 s = __ldg(&((const int4*)src)[i]);
    int  e = i * 4;

    if (s.x < INPUT_SIZE) {
        float m = __ldg(&x[s.x]) * __ldg(&w[e + 0]);
        atomicAdd(&g_acc[__ldg(&dst[e + 0])], m);
    }
    if (s.y < INPUT_SIZE) {
        float m = __ldg(&x[s.y]) * __ldg(&w[e + 1]);
        atomicAdd(&g_acc[__ldg(&dst[e + 1])], m);
    }
    if (s.z < INPUT_SIZE) {
        float m = __ldg(&x[s.z]) * __ldg(&w[e + 2]);
        atomicAdd(&g_acc[__ldg(&dst[e + 2])], m);
    }
    if (s.w < INPUT_SIZE) {
        float m = __ldg(&x[s.w]) * __ldg(&w[e + 3]);
        atomicAdd(&g_acc[__ldg(&dst[e + 3])], m);
    }
}

// ---------------------------------------------------------------------------
// Steps 2-3 edge pass: ENTIRE v lives in smem as fp16 (200KB). Single sweep
// of the edge stream, unconditional lanes: LDS gather -> fp32 FMUL -> RED.
// Persistent 148 CTAs x 1024 threads, 8 edges per thread-iteration.
// ---------------------------------------------------------------------------
__global__ void __launch_bounds__(1024, 1)
edge_fp16_kernel(const float* __restrict__ w,
                 const int*   __restrict__ src,
                 const int*   __restrict__ dst) {
    extern __shared__ __half sv[];    // N_NEURONS halves

    // Fill smem with the fp16 mirror of v (coalesced 16B loads).
    {
        const int4* vsrc = (const int4*)g_vh;       // 8 halves per int4
        int4*       vdst = (int4*)sv;
        const int   n16  = (N_NEURONS * 2) / 16;    // 12500
        for (int j = threadIdx.x; j < n16; j += blockDim.x)
            vdst[j] = __ldg(&vsrc[j]);
    }
    __syncthreads();

    const int4*   src4 = (const int4*)src;
    const int4*   dst4 = (const int4*)dst;
    const float4* w4   = (const float4*)w;
    const int nvec8  = E_EDGES / 8;
    const int stride = gridDim.x * blockDim.x;

    for (int i = blockIdx.x * blockDim.x + threadIdx.x; i < nvec8; i += stride) {
        int4   s0 = __ldg(&src4[2 * i]);
        int4   s1 = __ldg(&src4[2 * i + 1]);
        int4   d0 = __ldg(&dst4[2 * i]);
        int4   d1 = __ldg(&dst4[2 * i + 1]);
        float4 w0 = __ldg(&w4[2 * i]);
        float4 w1 = __ldg(&w4[2 * i + 1]);

        atomicAdd(&g_acc[d0.x], __half2float(sv[s0.x]) * w0.x);
        atomicAdd(&g_acc[d0.y], __half2float(sv[s0.y]) * w0.y);
        atomicAdd(&g_acc[d0.z], __half2float(sv[s0.z]) * w0.z);
        atomicAdd(&g_acc[d0.w], __half2float(sv[s0.w]) * w0.w);
        atomicAdd(&g_acc[d1.x], __half2float(sv[s1.x]) * w1.x);
        atomicAdd(&g_acc[d1.y], __half2float(sv[s1.y]) * w1.y);
        atomicAdd(&g_acc[d1.z], __half2float(sv[s1.z]) * w1.z);
        atomicAdd(&g_acc[d1.w], __half2float(sv[s1.w]) * w1.w);
    }
}

// ---------------------------------------------------------------------------
// Post pass: v = tanh(acc) (except outputs), fp16 mirror, re-seed acc with
// biases, optionally emit the output slice.
// ---------------------------------------------------------------------------
__global__ void post_kernel(const float* __restrict__ bias,
                            float* __restrict__ out,
                            int write_out) {
    int i = blockIdx.x * blockDim.x + threadIdx.x;
    if (i < N_NEURONS) {
        float a = g_acc[i];
        float v = (i < N_NEURONS - OUTPUT_SIZE) ? tanhf(a) : a;
        g_v[i]   = v;
        g_vh[i]  = __float2half(v);
        g_acc[i] = (i < INPUT_SIZE) ? 0.0f : bias[i - INPUT_SIZE];
        if (write_out && i >= N_NEURONS - OUTPUT_SIZE) {
            out[i - (N_NEURONS - OUTPUT_SIZE)] = v;
        }
    }
}

// ---------------------------------------------------------------------------
// Launcher — graph-capturable: kernel launches only.
// Input order: x, synapse_weights, neuron_biases, synapse_src, synapse_dst
// ---------------------------------------------------------------------------
extern "C" void kernel_launch(void* const* d_in, const int* in_sizes, int n_in,
                              void* d_out, int out_size) {
    const float* x    = (const float*)d_in[0];
    const float* w    = (const float*)d_in[1];
    const float* bias = (const float*)d_in[2];
    const int*   src  = (const int*)d_in[3];
    const int*   dst  = (const int*)d_in[4];
    float* out = (float*)d_out;

    cudaFuncSetAttribute(edge_fp16_kernel,
                         cudaFuncAttributeMaxDynamicSharedMemorySize,
                         VSMEM_BYTES);

    const int tpbN  = 256;
    const int gridN = (N_NEURONS + tpbN - 1) / tpbN;

    const int nvec  = E_EDGES / 4;
    const int tpbE  = 256;
    const int gridE = (nvec + tpbE - 1) / tpbE;

    init_kernel<<<gridN, tpbN>>>(bias);

    // Step 1: input-sparse edge pass (fp32 exact)
    edge_step1_kernel<<<gridE, tpbE>>>(x, w, src, dst);
    post_kernel<<<gridN, tpbN>>>(bias, out, 0);

    // Steps 2..3: single-pass sweep, whole v in smem as fp16
    for (int step = 1; step < STEPS; ++step) {
        edge_fp16_kernel<<<148, 1024, VSMEM_BYTES>>>(w, src, dst);
        post_kernel<<<gridN, tpbN>>>(bias, out, step == STEPS - 1 ? 1 : 0);
    }
}

// round 11
// speedup vs baseline: 2.8714x; 1.2015x over previous
#include <cuda_runtime.h>
#include <cuda_fp16.h>
#include <cuda_bf16.h>

#define N_NEURONS   100000
#define INPUT_SIZE  1024
#define OUTPUT_SIZE 256
#define E_EDGES     10000000
#define STEPS       3

#define OUT_BASE    (N_NEURONS - OUTPUT_SIZE)     // 99744
#define VSMEM_BYTES (N_NEURONS * 2)               // 200,000 B: all of v as fp16

// Persistent state in __device__ globals (no allocation allowed).
__device__ float  g_v[N_NEURONS];      // v after step 2 (fp32, for step-3 gather)
__device__ __half g_vh[N_NEURONS];     // v after step 1 (fp16, for step-2 smem)
__device__ float  g_acc[N_NEURONS];    // accumulator for steps 1-2
__device__ float  g_acc3[OUTPUT_SIZE]; // step-3 accumulator (outputs only)

// ---------------------------------------------------------------------------
// Init: seed g_acc with biases (step 1), seed g_acc3 with output biases.
// ---------------------------------------------------------------------------
__global__ void init_kernel(const float* __restrict__ bias) {
    int i = blockIdx.x * blockDim.x + threadIdx.x;
    if (i < N_NEURONS) {
        g_acc[i] = (i < INPUT_SIZE) ? 0.0f : bias[i - INPUT_SIZE];
    }
    if (i < OUTPUT_SIZE) {
        g_acc3[i] = bias[OUT_BASE + i - INPUT_SIZE];
    }
}

// ---------------------------------------------------------------------------
// Step 1: v is zero except v[0:1024]=x -> only ~1% of edges live (src<1024).
// Stream src only; touch w/dst/acc only for live edges. Full fp32.
// ---------------------------------------------------------------------------
__global__ void __launch_bounds__(256)
edge_step1_kernel(const float* __restrict__ x,
                  const float* __restrict__ w,
                  const int*   __restrict__ src,
                  const int*   __restrict__ dst) {
    const int nvec = E_EDGES / 4;
    int i = blockIdx.x * blockDim.x + threadIdx.x;
    if (i >= nvec) return;

    int4 s = __ldg(&((const int4*)src)[i]);
    int  e = i * 4;

    if (s.x < INPUT_SIZE) {
        float m = __ldg(&x[s.x]) * __ldg(&w[e + 0]);
        atomicAdd(&g_acc[__ldg(&dst[e + 0])], m);
    }
    if (s.y < INPUT_SIZE) {
        float m = __ldg(&x[s.y]) * __ldg(&w[e + 1]);
        atomicAdd(&g_acc[__ldg(&dst[e + 1])], m);
    }
    if (s.z < INPUT_SIZE) {
        float m = __ldg(&x[s.z]) * __ldg(&w[e + 2]);
        atomicAdd(&g_acc[__ldg(&dst[e + 2])], m);
    }
    if (s.w < INPUT_SIZE) {
        float m = __ldg(&x[s.w]) * __ldg(&w[e + 3]);
        atomicAdd(&g_acc[__ldg(&dst[e + 3])], m);
    }
}

// ---------------------------------------------------------------------------
// Step 2 (only dense step): whole v in smem as fp16; single sweep of edges.
// 4-edge groups with 1-deep prefetch pipeline; first group's LDGs issued
// BEFORE the smem fill to overlap stream latency with the fill.
// ---------------------------------------------------------------------------
__global__ void __launch_bounds__(1024, 1)
edge_dense_kernel(const float* __restrict__ w,
                  const int*   __restrict__ src,
                  const int*   __restrict__ dst) {
    extern __shared__ __half sv[];    // N_NEURONS halves

    const int4*   src4 = (const int4*)src;
    const int4*   dst4 = (const int4*)dst;
    const float4* w4   = (const float4*)w;
    const int nvec   = E_EDGES / 4;               // 2.5M groups
    const int stride = gridDim.x * blockDim.x;

    int  i    = blockIdx.x * blockDim.x + threadIdx.x;
    bool have = i < nvec;

    // Prefetch first group before the fill (overlaps ~500cyc DRAM latency).
    int4 s, d; float4 ww;
    if (have) {
        s  = __ldg(&src4[i]);
        d  = __ldg(&dst4[i]);
        ww = __ldg(&w4[i]);
    }

    // Fill smem with the fp16 mirror of v (coalesced 16B loads).
    {
        const int4* vsrc = (const int4*)g_vh;     // 8 halves per int4
        int4*       vdst = (int4*)sv;
        const int   n16  = (N_NEURONS * 2) / 16;  // 12500
        for (int j = threadIdx.x; j < n16; j += blockDim.x)
            vdst[j] = __ldg(&vsrc[j]);
    }
    __syncthreads();

    while (have) {
        int  in = i + stride;
        bool hn = in < nvec;
        int4 s2, d2; float4 w2;
        if (hn) {                                  // prefetch next group
            s2 = __ldg(&src4[in]);
            d2 = __ldg(&dst4[in]);
            w2 = __ldg(&w4[in]);
        }
        // process current group (overlaps the prefetch latency)
        atomicAdd(&g_acc[d.x], __half2float(sv[s.x]) * ww.x);
        atomicAdd(&g_acc[d.y], __half2float(sv[s.y]) * ww.y);
        atomicAdd(&g_acc[d.z], __half2float(sv[s.z]) * ww.z);
        atomicAdd(&g_acc[d.w], __half2float(sv[s.w]) * ww.w);

        s = s2; d = d2; ww = w2; i = in; have = hn;
    }
}

// ---------------------------------------------------------------------------
// Step 3: only edges with dst in the output window matter (~0.26% of E),
// because the result is v[N-256:] and outputs get no tanh.
// Stream dst only; gather fp32 v for live lanes; RED into g_acc3.
// ---------------------------------------------------------------------------
__global__ void __launch_bounds__(256)
edge_step3_kernel(const float* __restrict__ w,
                  const int*   __restrict__ src,
                  const int*   __restrict__ dst) {
    const int nvec = E_EDGES / 4;
    int i = blockIdx.x * blockDim.x + threadIdx.x;
    if (i >= nvec) return;

    int4 d = __ldg(&((const int4*)dst)[i]);
    int  e = i * 4;

    if (d.x >= OUT_BASE) {
        float m = __ldg(&g_v[__ldg(&src[e + 0])]) * __ldg(&w[e + 0]);
        atomicAdd(&g_acc3[d.x - OUT_BASE], m);
    }
    if (d.y >= OUT_BASE) {
        float m = __ldg(&g_v[__ldg(&src[e + 1])]) * __ldg(&w[e + 1]);
        atomicAdd(&g_acc3[d.y - OUT_BASE], m);
    }
    if (d.z >= OUT_BASE) {
        float m = __ldg(&g_v[__ldg(&src[e + 2])]) * __ldg(&w[e + 2]);
        atomicAdd(&g_acc3[d.z - OUT_BASE], m);
    }
    if (d.w >= OUT_BASE) {
        float m = __ldg(&g_v[__ldg(&src[e + 3])]) * __ldg(&w[e + 3]);
        atomicAdd(&g_acc3[d.w - OUT_BASE], m);
    }
}

// ---------------------------------------------------------------------------
// Post pass after steps 1 and 2.
//   mode 1 (after step 1): write fp16 mirror for step-2 smem; reseed g_acc.
//   mode 2 (after step 2): write fp32 g_v for step-3 gather.
// ---------------------------------------------------------------------------
__global__ void post_kernel(const float* __restrict__ bias, int mode) {
    int i = blockIdx.x * blockDim.x + threadIdx.x;
    if (i < N_NEURONS) {
        float a = g_acc[i];
        float v = (i < OUT_BASE) ? tanhf(a) : a;
        if (mode == 1) {
            g_vh[i]  = __float2half(v);
            g_acc[i] = (i < INPUT_SIZE) ? 0.0f : bias[i - INPUT_SIZE];
        } else {
            g_v[i] = v;
        }
    }
}

// ---------------------------------------------------------------------------
// Finalize: emit the 256 outputs (identity, biases already seeded in g_acc3).
// ---------------------------------------------------------------------------
__global__ void finalize_kernel(float* __restrict__ out) {
    int i = threadIdx.x;
    if (i < OUTPUT_SIZE) out[i] = g_acc3[i];
}

// ---------------------------------------------------------------------------
// Launcher — graph-capturable: kernel launches only.
// Input order: x, synapse_weights, neuron_biases, synapse_src, synapse_dst
// ---------------------------------------------------------------------------
extern "C" void kernel_launch(void* const* d_in, const int* in_sizes, int n_in,
                              void* d_out, int out_size) {
    const float* x    = (const float*)d_in[0];
    const float* w    = (const float*)d_in[1];
    const float* bias = (const float*)d_in[2];
    const int*   src  = (const int*)d_in[3];
    const int*   dst  = (const int*)d_in[4];
    float* out = (float*)d_out;

    cudaFuncSetAttribute(edge_dense_kernel,
                         cudaFuncAttributeMaxDynamicSharedMemorySize,
                         VSMEM_BYTES);

    const int tpbN  = 256;
    const int gridN = (N_NEURONS + tpbN - 1) / tpbN;

    const int nvec  = E_EDGES / 4;
    const int tpbE  = 256;
    const int gridE = (nvec + tpbE - 1) / tpbE;

    init_kernel<<<gridN, tpbN>>>(bias);

    // Step 1: input-sparse (src < 1024)
    edge_step1_kernel<<<gridE, tpbE>>>(x, w, src, dst);
    post_kernel<<<gridN, tpbN>>>(bias, 1);

    // Step 2: dense sweep, whole v in smem as fp16, pipelined stream
    edge_dense_kernel<<<148, 1024, VSMEM_BYTES>>>(w, src, dst);
    post_kernel<<<gridN, tpbN>>>(bias, 2);

    // Step 3: output-sparse (dst >= N-256), fp32 gather
    edge_step3_kernel<<<gridE, tpbE>>>(w, src, dst);
    finalize_kernel<<<1, OUTPUT_SIZE>>>(out);
}

// round 12
// speedup vs baseline: 5.1943x; 1.8090x over previous
#include <cuda_runtime.h>
#include <cuda_fp16.h>
#include <cuda_bf16.h>

#define N_NEURONS   100000
#define INPUT_SIZE  1024
#define OUTPUT_SIZE 256
#define E_EDGES     10000000

#define OUT_BASE    (N_NEURONS - OUTPUT_SIZE)     // 99744
#define NBM_WORDS   ((N_NEURONS + 31) / 32)       // 3125 bitmap words
#define BM_BYTES_AL 12512                         // bitmap smem bytes, 16B-aligned
#define SMEM_TOTAL  (BM_BYTES_AL + N_NEURONS * 2) // 212,512 B

// Persistent state in __device__ globals (no allocation allowed).
__device__ float    g_v[N_NEURONS];      // v after step 2 (fp32, step-3 gather)
__device__ __half   g_vh[N_NEURONS];     // v after step 1 (fp16, step-2 smem)
__device__ float    g_acc[N_NEURONS];    // accumulator for steps 1-2
__device__ float    g_acc3[OUTPUT_SIZE]; // step-3 accumulator (outputs only)
__device__ unsigned g_bm[NBM_WORDS];     // "needed after step 2" bitmap

// ---------------------------------------------------------------------------
// Init: seed g_acc with biases, g_acc3 with output biases, clear bitmap.
// ---------------------------------------------------------------------------
__global__ void init_kernel(const float* __restrict__ bias) {
    int i = blockIdx.x * blockDim.x + threadIdx.x;
    if (i < N_NEURONS) {
        g_acc[i] = (i < INPUT_SIZE) ? 0.0f : bias[i - INPUT_SIZE];
    }
    if (i < OUTPUT_SIZE) {
        g_acc3[i] = bias[OUT_BASE + i - INPUT_SIZE];
    }
    if (i < NBM_WORDS) {
        g_bm[i] = 0u;
    }
}

// ---------------------------------------------------------------------------
// Mark pass: neurons whose step-2 value is actually read by step 3 are
// exactly { src[e] : dst[e] >= OUT_BASE } (~0.26% of edges live).
// Stream dst; for live edges read src and set the bitmap bit.
// ---------------------------------------------------------------------------
__global__ void __launch_bounds__(256)
mark_kernel(const int* __restrict__ src,
            const int* __restrict__ dst) {
    const int nvec = E_EDGES / 4;
    int i = blockIdx.x * blockDim.x + threadIdx.x;
    if (i >= nvec) return;

    int4 d = __ldg(&((const int4*)dst)[i]);
    int  e = i * 4;

    if (d.x >= OUT_BASE) { unsigned s = __ldg(&src[e + 0]); atomicOr(&g_bm[s >> 5], 1u << (s & 31)); }
    if (d.y >= OUT_BASE) { unsigned s = __ldg(&src[e + 1]); atomicOr(&g_bm[s >> 5], 1u << (s & 31)); }
    if (d.z >= OUT_BASE) { unsigned s = __ldg(&src[e + 2]); atomicOr(&g_bm[s >> 5], 1u << (s & 31)); }
    if (d.w >= OUT_BASE) { unsigned s = __ldg(&src[e + 3]); atomicOr(&g_bm[s >> 5], 1u << (s & 31)); }
}

// ---------------------------------------------------------------------------
// Step 1: v is zero except v[0:1024]=x -> only ~1% of edges live (src<1024).
// ---------------------------------------------------------------------------
__global__ void __launch_bounds__(256)
edge_step1_kernel(const float* __restrict__ x,
                  const float* __restrict__ w,
                  const int*   __restrict__ src,
                  const int*   __restrict__ dst) {
    const int nvec = E_EDGES / 4;
    int i = blockIdx.x * blockDim.x + threadIdx.x;
    if (i >= nvec) return;

    int4 s = __ldg(&((const int4*)src)[i]);
    int  e = i * 4;

    if (s.x < INPUT_SIZE) {
        float m = __ldg(&x[s.x]) * __ldg(&w[e + 0]);
        atomicAdd(&g_acc[__ldg(&dst[e + 0])], m);
    }
    if (s.y < INPUT_SIZE) {
        float m = __ldg(&x[s.y]) * __ldg(&w[e + 1]);
        atomicAdd(&g_acc[__ldg(&dst[e + 1])], m);
    }
    if (s.z < INPUT_SIZE) {
        float m = __ldg(&x[s.z]) * __ldg(&w[e + 2]);
        atomicAdd(&g_acc[__ldg(&dst[e + 2])], m);
    }
    if (s.w < INPUT_SIZE) {
        float m = __ldg(&x[s.w]) * __ldg(&w[e + 3]);
        atomicAdd(&g_acc[__ldg(&dst[e + 3])], m);
    }
}

// ---------------------------------------------------------------------------
// Step 2: whole v in smem as fp16 + needed-bitmap in smem. Single sweep of
// the edge stream (unconditional int4 loads); gather+RED only for edges whose
// dst survives the backward slice (~23% of lanes). R9 loop shape (no manual
// pipeline — it spills at the 64-reg/1024-thread ceiling).
// ---------------------------------------------------------------------------
__global__ void __launch_bounds__(1024, 1)
edge_dense_kernel(const float* __restrict__ w,
                  const int*   __restrict__ src,
                  const int*   __restrict__ dst) {
    extern __shared__ unsigned smem_raw[];
    unsigned* sbm = smem_raw;                                   // NBM_WORDS
    __half*   sv  = (__half*)((char*)smem_raw + BM_BYTES_AL);   // N_NEURONS

    // Fill bitmap (12.5KB) and v fp16 mirror (200KB), coalesced.
    for (int j = threadIdx.x; j < NBM_WORDS; j += blockDim.x)
        sbm[j] = __ldg(&g_bm[j]);
    {
        const int4* vsrc = (const int4*)g_vh;       // 8 halves per int4
        int4*       vdst = (int4*)sv;
        const int   n16  = (N_NEURONS * 2) / 16;    // 12500
        for (int j = threadIdx.x; j < n16; j += blockDim.x)
            vdst[j] = __ldg(&vsrc[j]);
    }
    __syncthreads();

    const int4*   src4 = (const int4*)src;
    const int4*   dst4 = (const int4*)dst;
    const float4* w4   = (const float4*)w;
    const int nvec8  = E_EDGES / 8;
    const int stride = gridDim.x * blockDim.x;

    for (int i = blockIdx.x * blockDim.x + threadIdx.x; i < nvec8; i += stride) {
        int4   s0 = __ldg(&src4[2 * i]);
        int4   s1 = __ldg(&src4[2 * i + 1]);
        int4   d0 = __ldg(&dst4[2 * i]);
        int4   d1 = __ldg(&dst4[2 * i + 1]);
        float4 w0 = __ldg(&w4[2 * i]);
        float4 w1 = __ldg(&w4[2 * i + 1]);

        #define EDGE(S, D, W) do {                                          \
            unsigned _d = (unsigned)(D);                                    \
            if ((sbm[_d >> 5] >> (_d & 31)) & 1u)                           \
                atomicAdd(&g_acc[_d], __half2float(sv[(S)]) * (W));         \
        } while (0)

        EDGE(s0.x, d0.x, w0.x);
        EDGE(s0.y, d0.y, w0.y);
        EDGE(s0.z, d0.z, w0.z);
        EDGE(s0.w, d0.w, w0.w);
        EDGE(s1.x, d1.x, w1.x);
        EDGE(s1.y, d1.y, w1.y);
        EDGE(s1.z, d1.z, w1.z);
        EDGE(s1.w, d1.w, w1.w);
        #undef EDGE
    }
}

// ---------------------------------------------------------------------------
// Step 3: only edges with dst in the output window matter (~0.26% of E).
// Stream dst only; gather fp32 v for live lanes; RED into g_acc3.
// ---------------------------------------------------------------------------
__global__ void __launch_bounds__(256)
edge_step3_kernel(const float* __restrict__ w,
                  const int*   __restrict__ src,
                  const int*   __restrict__ dst) {
    const int nvec = E_EDGES / 4;
    int i = blockIdx.x * blockDim.x + threadIdx.x;
    if (i >= nvec) return;

    int4 d = __ldg(&((const int4*)dst)[i]);
    int  e = i * 4;

    if (d.x >= OUT_BASE) {
        float m = __ldg(&g_v[__ldg(&src[e + 0])]) * __ldg(&w[e + 0]);
        atomicAdd(&g_acc3[d.x - OUT_BASE], m);
    }
    if (d.y >= OUT_BASE) {
        float m = __ldg(&g_v[__ldg(&src[e + 1])]) * __ldg(&w[e + 1]);
        atomicAdd(&g_acc3[d.y - OUT_BASE], m);
    }
    if (d.z >= OUT_BASE) {
        float m = __ldg(&g_v[__ldg(&src[e + 2])]) * __ldg(&w[e + 2]);
        atomicAdd(&g_acc3[d.z - OUT_BASE], m);
    }
    if (d.w >= OUT_BASE) {
        float m = __ldg(&g_v[__ldg(&src[e + 3])]) * __ldg(&w[e + 3]);
        atomicAdd(&g_acc3[d.w - OUT_BASE], m);
    }
}

// ---------------------------------------------------------------------------
// Post pass.
//   mode 1 (after step 1): fp16 mirror for step-2 smem; reseed g_acc.
//   mode 2 (after step 2): fp32 g_v for step-3 gather. (Values for neurons
//   outside the needed-set are garbage — provably never read.)
// ---------------------------------------------------------------------------
__global__ void post_kernel(const float* __restrict__ bias, int mode) {
    int i = blockIdx.x * blockDim.x + threadIdx.x;
    if (i < N_NEURONS) {
        float a = g_acc[i];
        float v = (i < OUT_BASE) ? tanhf(a) : a;
        if (mode == 1) {
            g_vh[i]  = __float2half(v);
            g_acc[i] = (i < INPUT_SIZE) ? 0.0f : bias[i - INPUT_SIZE];
        } else {
            g_v[i] = v;
        }
    }
}

// ---------------------------------------------------------------------------
// Finalize: emit the 256 outputs (identity; biases already seeded).
// ---------------------------------------------------------------------------
__global__ void finalize_kernel(float* __restrict__ out) {
    int i = threadIdx.x;
    if (i < OUTPUT_SIZE) out[i] = g_acc3[i];
}

// ---------------------------------------------------------------------------
// Launcher — graph-capturable: kernel launches only.
// Input order: x, synapse_weights, neuron_biases, synapse_src, synapse_dst
// ---------------------------------------------------------------------------
extern "C" void kernel_launch(void* const* d_in, const int* in_sizes, int n_in,
                              void* d_out, int out_size) {
    const float* x    = (const float*)d_in[0];
    const float* w    = (const float*)d_in[1];
    const float* bias = (const float*)d_in[2];
    const int*   src  = (const int*)d_in[3];
    const int*   dst  = (const int*)d_in[4];
    float* out = (float*)d_out;

    cudaFuncSetAttribute(edge_dense_kernel,
                         cudaFuncAttributeMaxDynamicSharedMemorySize,
                         SMEM_TOTAL);

    const int tpbN  = 256;
    const int gridN = (N_NEURONS + tpbN - 1) / tpbN;

    const int nvec  = E_EDGES / 4;
    const int tpbE  = 256;
    const int gridE = (nvec + tpbE - 1) / tpbE;

    init_kernel<<<gridN, tpbN>>>(bias);

    // Backward slice: which neurons' step-2 values does step 3 read?
    mark_kernel<<<gridE, tpbE>>>(src, dst);

    // Step 1: input-sparse (src < 1024)
    edge_step1_kernel<<<gridE, tpbE>>>(x, w, src, dst);
    post_kernel<<<gridN, tpbN>>>(bias, 1);

    // Step 2: sliced dense sweep, whole v + bitmap in smem
    edge_dense_kernel<<<148, 1024, SMEM_TOTAL>>>(w, src, dst);
    post_kernel<<<gridN, tpbN>>>(bias, 2);

    // Step 3: output-sparse (dst >= N-256), fp32 gather
    edge_step3_kernel<<<gridE, tpbE>>>(w, src, dst);
    finalize_kernel<<<1, OUTPUT_SIZE>>>(out);
}

// round 17
// speedup vs baseline: 5.6077x; 1.0796x over previous
#include <cuda_runtime.h>
#include <cuda_fp16.h>
#include <cuda_bf16.h>

#define N_NEURONS   100000
#define INPUT_SIZE  1024
#define OUTPUT_SIZE 256
#define E_EDGES     10000000

#define OUT_BASE    (N_NEURONS - OUTPUT_SIZE)     // 99744
#define NBM_WORDS   ((N_NEURONS + 31) / 32)       // 3125 bitmap words
#define BM_BYTES_AL 12512                         // bitmap smem bytes, 16B-aligned
#define SMEM_TOTAL  (BM_BYTES_AL + N_NEURONS * 2) // 212,512 B
#define LIST_CAP    1000000                       // live-edge list capacity (~39x expected)

// Persistent state in __device__ globals (no allocation allowed).
__device__ float    g_acc[N_NEURONS];    // accumulator (steps 1-2)
__device__ __half   g_vh[N_NEURONS];     // v after step 1 (fp16, step-2 smem)
__device__ float    g_acc3[OUTPUT_SIZE]; // step-3 accumulator (outputs only)
__device__ unsigned g_bm[NBM_WORDS];     // "needed after step 2" bitmap
__device__ unsigned g_list[LIST_CAP];    // packed live step-3 edges: (e<<8)|outIdx
__device__ unsigned g_cnt;               // live-edge count

// ---------------------------------------------------------------------------
// Init: seed g_acc with biases, g_acc3 with output biases, clear bitmap+count.
// ---------------------------------------------------------------------------
__global__ void init_kernel(const float* __restrict__ bias) {
    int i = blockIdx.x * blockDim.x + threadIdx.x;
    if (i < N_NEURONS) {
        g_acc[i] = (i < INPUT_SIZE) ? 0.0f : bias[i - INPUT_SIZE];
    }
    if (i < OUTPUT_SIZE) {
        g_acc3[i] = bias[OUT_BASE + i - INPUT_SIZE];
    }
    if (i < NBM_WORDS) {
        g_bm[i] = 0u;
    }
    if (i == 0) g_cnt = 0u;
}

// ---------------------------------------------------------------------------
// Fused scan: single sweep over src4+dst4 (80MB) doing BOTH
//  (a) step 1: edges with src<1024 are the only live ones (v is x-padded-0);
//  (b) backward slice: edges with dst>=OUT_BASE are what step 3 reads ->
//      mark src in the bitmap and append the packed edge to the list.
// ---------------------------------------------------------------------------
__global__ void __launch_bounds__(256)
scan_kernel(const float* __restrict__ x,
            const float* __restrict__ w,
            const int*   __restrict__ src,
            const int*   __restrict__ dst) {
    const int nvec = E_EDGES / 4;
    int i = blockIdx.x * blockDim.x + threadIdx.x;
    if (i >= nvec) return;

    int4 s = __ldg(&((const int4*)src)[i]);
    int4 d = __ldg(&((const int4*)dst)[i]);
    int  e = i * 4;

    #define LANE(S, D, K) do {                                               \
        if ((S) < INPUT_SIZE) {                                              \
            float m = __ldg(&x[(S)]) * __ldg(&w[e + (K)]);                   \
            atomicAdd(&g_acc[(D)], m);                                       \
        }                                                                    \
        if ((D) >= OUT_BASE) {                                               \
            unsigned us = (unsigned)(S);                                     \
            atomicOr(&g_bm[us >> 5], 1u << (us & 31));                       \
            unsigned idx = atomicAdd(&g_cnt, 1u);                            \
            if (idx < LIST_CAP)                                              \
                g_list[idx] = ((unsigned)(e + (K)) << 8) |                   \
                              (unsigned)((D) - OUT_BASE);                    \
        }                                                                    \
    } while (0)

    LANE(s.x, d.x, 0);
    LANE(s.y, d.y, 1);
    LANE(s.z, d.z, 2);
    LANE(s.w, d.w, 3);
    #undef LANE
}

// ---------------------------------------------------------------------------
// Post (after step 1): v1 = tanh(acc) masked; store fp16 mirror for step-2
// smem; reseed acc with biases. Vectorized 4 neurons/thread (N % 4 == 0,
// INPUT_SIZE and OUT_BASE are 4-aligned).
// ---------------------------------------------------------------------------
__global__ void __launch_bounds__(256)
post1_kernel(const float* __restrict__ bias) {
    int t  = blockIdx.x * blockDim.x + threadIdx.x;
    int i4 = t * 4;
    if (i4 >= N_NEURONS) return;

    float4 a = *(const float4*)&g_acc[i4];
    float v0 = (i4 + 0 < OUT_BASE) ? tanhf(a.x) : a.x;
    float v1 = (i4 + 1 < OUT_BASE) ? tanhf(a.y) : a.y;
    float v2 = (i4 + 2 < OUT_BASE) ? tanhf(a.z) : a.z;
    float v3 = (i4 + 3 < OUT_BASE) ? tanhf(a.w) : a.w;

    __half2 hpair[2];
    hpair[0] = __floats2half2_rn(v0, v1);
    hpair[1] = __floats2half2_rn(v2, v3);
    *(uint2*)&g_vh[i4] = *(const uint2*)hpair;

    float4 r;
    r.x = (i4 + 0 < INPUT_SIZE) ? 0.0f : __ldg(&bias[i4 + 0 - INPUT_SIZE]);
    r.y = (i4 + 1 < INPUT_SIZE) ? 0.0f : __ldg(&bias[i4 + 1 - INPUT_SIZE]);
    r.z = (i4 + 2 < INPUT_SIZE) ? 0.0f : __ldg(&bias[i4 + 2 - INPUT_SIZE]);
    r.w = (i4 + 3 < INPUT_SIZE) ? 0.0f : __ldg(&bias[i4 + 3 - INPUT_SIZE]);
    *(float4*)&g_acc[i4] = r;
}

// ---------------------------------------------------------------------------
// Step 2: whole v in smem as fp16 + needed-bitmap in smem. Single sweep of
// the edge stream (unconditional int4 loads); gather+RED only for edges whose
// dst survives the backward slice (~23% of lanes).
// ---------------------------------------------------------------------------
__global__ void __launch_bounds__(1024, 1)
edge_dense_kernel(const float* __restrict__ w,
                  const int*   __restrict__ src,
                  const int*   __restrict__ dst) {
    extern __shared__ unsigned smem_raw[];
    unsigned* sbm = smem_raw;                                   // NBM_WORDS
    __half*   sv  = (__half*)((char*)smem_raw + BM_BYTES_AL);   // N_NEURONS

    for (int j = threadIdx.x; j < NBM_WORDS; j += blockDim.x)
        sbm[j] = __ldg(&g_bm[j]);
    {
        const int4* vsrc = (const int4*)g_vh;       // 8 halves per int4
        int4*       vdst = (int4*)sv;
        const int   n16  = (N_NEURONS * 2) / 16;    // 12500
        for (int j = threadIdx.x; j < n16; j += blockDim.x)
            vdst[j] = __ldg(&vsrc[j]);
    }
    __syncthreads();

    const int4*   src4 = (const int4*)src;
    const int4*   dst4 = (const int4*)dst;
    const float4* w4   = (const float4*)w;
    const int nvec8  = E_EDGES / 8;
    const int stride = gridDim.x * blockDim.x;

    for (int i = blockIdx.x * blockDim.x + threadIdx.x; i < nvec8; i += stride) {
        int4   s0 = __ldg(&src4[2 * i]);
        int4   s1 = __ldg(&src4[2 * i + 1]);
        int4   d0 = __ldg(&dst4[2 * i]);
        int4   d1 = __ldg(&dst4[2 * i + 1]);
        float4 w0 = __ldg(&w4[2 * i]);
        float4 w1 = __ldg(&w4[2 * i + 1]);

        #define EDGE(S, D, W) do {                                          \
            unsigned _d = (unsigned)(D);                                    \
            if ((sbm[_d >> 5] >> (_d & 31)) & 1u)                           \
                atomicAdd(&g_acc[_d], __half2float(sv[(S)]) * (W));         \
        } while (0)

        EDGE(s0.x, d0.x, w0.x);
        EDGE(s0.y, d0.y, w0.y);
        EDGE(s0.z, d0.z, w0.z);
        EDGE(s0.w, d0.w, w0.w);
        EDGE(s1.x, d1.x, w1.x);
        EDGE(s1.y, d1.y, w1.y);
        EDGE(s1.z, d1.z, w1.z);
        EDGE(s1.w, d1.w, w1.w);
        #undef EDGE
    }
}

// ---------------------------------------------------------------------------
// Step 3: iterate the compacted live-edge list (~25.6K entries). Gather
// acc[src] (complete for all marked srcs), apply tanh mask inline, RED into
// g_acc3. Eliminates both the dst re-scan and the post(2) pass.
// ---------------------------------------------------------------------------
__global__ void __launch_bounds__(256)
step3_kernel(const float* __restrict__ w,
             const int*   __restrict__ src) {
    unsigned n = g_cnt;
    if (n > LIST_CAP) n = LIST_CAP;
    int stride = gridDim.x * blockDim.x;
    for (unsigned j = blockIdx.x * blockDim.x + threadIdx.x; j < n; j += stride) {
        unsigned p = g_list[j];
        int e = (int)(p >> 8);
        int o = (int)(p & 255u);
        int s = __ldg(&src[e]);
        float a = g_acc[s];
        float v = (s < OUT_BASE) ? tanhf(a) : a;
        atomicAdd(&g_acc3[o], v * __ldg(&w[e]));
    }
}

// ---------------------------------------------------------------------------
// Finalize: emit the 256 outputs (identity; biases already seeded).
// ---------------------------------------------------------------------------
__global__ void finalize_kernel(float* __restrict__ out) {
    int i = threadIdx.x;
    if (i < OUTPUT_SIZE) out[i] = g_acc3[i];
}

// ---------------------------------------------------------------------------
// Launcher — graph-capturable: kernel launches only.
// Input order: x, synapse_weights, neuron_biases, synapse_src, synapse_dst
// ---------------------------------------------------------------------------
extern "C" void kernel_launch(void* const* d_in, const int* in_sizes, int n_in,
                              void* d_out, int out_size) {
    const float* x    = (const float*)d_in[0];
    const float* w    = (const float*)d_in[1];
    const float* bias = (const float*)d_in[2];
    const int*   src  = (const int*)d_in[3];
    const int*   dst  = (const int*)d_in[4];
    float* out = (float*)d_out;

    cudaFuncSetAttribute(edge_dense_kernel,
                         cudaFuncAttributeMaxDynamicSharedMemorySize,
                         SMEM_TOTAL);

    const int tpbN  = 256;
    const int gridN = (N_NEURONS + tpbN - 1) / tpbN;
    const int gridP = (N_NEURONS / 4 + tpbN - 1) / tpbN;

    const int nvec  = E_EDGES / 4;
    const int tpbE  = 256;
    const int gridE = (nvec + tpbE - 1) / tpbE;

    init_kernel<<<gridN, tpbN>>>(bias);

    // Fused: step 1 (src<1024) + backward slice (bitmap + live-edge list)
    scan_kernel<<<gridE, tpbE>>>(x, w, src, dst);
    post1_kernel<<<gridP, tpbN>>>(bias);

    // Step 2: sliced dense sweep, whole v + bitmap in smem
    edge_dense_kernel<<<148, 1024, SMEM_TOTAL>>>(w, src, dst);

    // Step 3: compacted list, tanh applied at gather time
    step3_kernel<<<128, 256>>>(w, src);
    finalize_kernel<<<1, OUTPUT_SIZE>>>(out);
}